// round 12
// baseline (speedup 1.0000x reference)
#include <cuda_runtime.h>
#include <cuda_fp16.h>
#include <cstdint>

#define F_IN     256
#define F_OUT    128
#define MAX_N    100352            // 1024 * 98, covers 100000
#define MAX_E    1600000
#define CHUNK    98                // elements per thread in fused scan

// Static scratch — __device__ globals (no allocation allowed).
__device__ __half g_h16[(size_t)100000 * F_OUT];  // h = x @ W, fp16 (25.6 MB)
__device__ __half g_Bh16[F_IN * F_OUT];           // W^T fp16, [n][k]
__device__ int   g_cnt[MAX_N];
__device__ int   g_off[MAX_N + 1];
__device__ int   g_cur[MAX_N];
__device__ int2  g_edge[MAX_E];                   // (src, val_bits) CSR order

// ---------------------------------------------------------------------------
// CSR build: zero -> count -> fused scan (ONE kernel) -> fill(packed)
// ---------------------------------------------------------------------------
__global__ void zero_cnt_kernel(int n_pad) {
    int i = blockIdx.x * blockDim.x + threadIdx.x;
    if (i < n_pad) g_cnt[i] = 0;
}

__global__ void count_kernel(const int* __restrict__ edge_dst, int E) {
    int i = blockIdx.x * blockDim.x + threadIdx.x;
    if (i < E) atomicAdd(&g_cnt[edge_dst[i]], 1);
}

// Single-block exclusive scan over MAX_N counters. 1024 threads x 98 elems.
__global__ __launch_bounds__(1024)
void scan_fused_kernel(int E) {
    __shared__ int s[1024];
    const int t = threadIdx.x;
    const int base = t * CHUNK;

    // pass 1: per-thread total
    int sum = 0;
    #pragma unroll 7
    for (int i = 0; i < CHUNK; i++) sum += g_cnt[base + i];
    s[t] = sum;
    __syncthreads();

    // block exclusive scan of 1024 partial sums
    #pragma unroll
    for (int off = 1; off < 1024; off <<= 1) {
        int tmp = (t >= off) ? s[t - off] : 0;
        __syncthreads();
        s[t] += tmp;
        __syncthreads();
    }
    int run = s[t] - sum;   // exclusive prefix for this thread's chunk

    // pass 2: write offsets + cursors
    #pragma unroll 7
    for (int i = 0; i < CHUNK; i++) {
        g_off[base + i] = run;
        g_cur[base + i] = run;
        run += g_cnt[base + i];
    }
    if (t == 1023) g_off[MAX_N] = E;   // == run for the last thread
}

__global__ void fill_kernel(const int* __restrict__ edge_dst,
                            const int* __restrict__ edge_src,
                            const float* __restrict__ edge_vals, int E) {
    int i = blockIdx.x * blockDim.x + threadIdx.x;
    if (i < E) {
        int p = atomicAdd(&g_cur[edge_dst[i]], 1);
        g_edge[p] = make_int2(edge_src[i], __float_as_int(edge_vals[i]));
    }
}

// ---------------------------------------------------------------------------
// Kernel 2a: W transpose to fp16:  Bh[n][k] = fp16(w[k][n])
// ---------------------------------------------------------------------------
__global__ void wsplit_kernel(const float* __restrict__ w,
                              __half* __restrict__ bh) {
    int k = blockIdx.x;        // 0..255
    int n = threadIdx.x;       // 0..127
    bh[n * F_IN + k] = __float2half_rn(w[k * F_OUT + n]);
}

// ---------------------------------------------------------------------------
// Kernel 2b: mma.sync fp16 GEMM (single pass) — unchanged from passing R10.
// ---------------------------------------------------------------------------
#define KC       32
#define NCHUNK   (F_IN / KC)       // 8
#define ASU      20                // u32 per SMEM row (16 data + 4 pad)
#define SM_A     0
#define SM_BH    (128 * ASU)
#define GEMM_SMEM_BYTES (2 * 128 * ASU * 4)   // 20480

__device__ __forceinline__ uint32_t pack_h2(float a, float b) {
    __half2 t = __floats2half2_rn(a, b);   // .x = a (low half)
    return *(uint32_t*)&t;
}

__device__ __forceinline__ void mma_f16(float* d, const uint32_t* a,
                                        const uint32_t* b) {
    asm volatile(
        "mma.sync.aligned.m16n8k16.row.col.f32.f16.f16.f32 "
        "{%0, %1, %2, %3}, {%4, %5, %6, %7}, {%8, %9}, {%0, %1, %2, %3};"
        : "+f"(d[0]), "+f"(d[1]), "+f"(d[2]), "+f"(d[3])
        : "r"(a[0]), "r"(a[1]), "r"(a[2]), "r"(a[3]), "r"(b[0]), "r"(b[1]));
}

__global__ __launch_bounds__(256, 2)
void gemm_mma_kernel(const float* __restrict__ x,
                     const __half* __restrict__ bh_g,
                     __half* __restrict__ h16, int M) {
    extern __shared__ uint32_t smu[];
    const int tid  = threadIdx.x;
    const int wid  = tid >> 5;
    const int lane = tid & 31;
    const int g = lane >> 2;
    const int t = lane & 3;
    const int wm = wid & 3;
    const int wn = wid >> 2;
    const int block_row = blockIdx.x * 128;

    const uint32_t* bhu = (const uint32_t*)bh_g;   // [n][128] u32 rows
    uint32_t* hu = (uint32_t*)h16;                 // h as u32 (half2) words

    float acc[2][8][4];
    #pragma unroll
    for (int i = 0; i < 2; i++)
        #pragma unroll
        for (int j = 0; j < 8; j++)
            #pragma unroll
            for (int q = 0; q < 4; q++) acc[i][j][q] = 0.0f;

    for (int c = 0; c < NCHUNK; c++) {
        if (c > 0) __syncthreads();
        // ---- A: 128 rows x 32 k; fp32 -> fp16, packed u32 pairs ----
        #pragma unroll
        for (int i = 0; i < 4; i++) {
            int fidx = i * 256 + tid;          // 1024 float4 slots
            int row = fidx >> 3, c4 = fidx & 7;
            int grow = block_row + row;
            float4 v = make_float4(0.f, 0.f, 0.f, 0.f);
            if (grow < M)
                v = *(const float4*)(x + (size_t)grow * F_IN + c * KC + c4 * 4);
            uint32_t base = row * ASU + c4 * 2;
            *(uint2*)&smu[SM_A + base] =
                make_uint2(pack_h2(v.x, v.y), pack_h2(v.z, v.w));
        }
        // ---- B: 128 n-rows x 32 k (fp16 in gmem) ----
        {
            int fidx = tid;                    // 256 uint4 slots
            int row = fidx >> 1, q = fidx & 1;
            const size_t go = (size_t)row * (F_IN / 2) + c * (KC / 2) + q * 8;
            uint4 vh0 = *(const uint4*)(bhu + go);
            uint4 vh1 = *(const uint4*)(bhu + go + 4);
            uint32_t base = row * ASU + q * 8;
            *(uint4*)&smu[SM_BH + base] = vh0;
            *(uint4*)&smu[SM_BH + base + 4] = vh1;
        }
        __syncthreads();

        #pragma unroll
        for (int kp = 0; kp < KC / 2; kp += 8) {   // two k16 steps
            uint32_t a[2][4];
            #pragma unroll
            for (int mt = 0; mt < 2; mt++) {
                int r0 = (wm * 32 + mt * 16 + g) * ASU + kp + t;
                int r8 = (wm * 32 + mt * 16 + g + 8) * ASU + kp + t;
                a[mt][0] = smu[SM_A + r0];
                a[mt][1] = smu[SM_A + r8];
                a[mt][2] = smu[SM_A + r0 + 4];
                a[mt][3] = smu[SM_A + r8 + 4];
            }
            #pragma unroll
            for (int nt = 0; nt < 8; nt++) {
                int nrow = (wn * 64 + nt * 8 + g) * ASU + kp + t;
                uint32_t bh[2];
                bh[0] = smu[SM_BH + nrow];
                bh[1] = smu[SM_BH + nrow + 4];
                #pragma unroll
                for (int mt = 0; mt < 2; mt++)
                    mma_f16(acc[mt][nt], a[mt], bh);
            }
        }
    }

    // ---- writeback h as fp16 (one u32 = half2 per fragment pair) ----
    #pragma unroll
    for (int mt = 0; mt < 2; mt++) {
        int row0 = block_row + wm * 32 + mt * 16 + g;
        int row8 = row0 + 8;
        #pragma unroll
        for (int nt = 0; nt < 8; nt++) {
            int col = wn * 64 + nt * 8 + 2 * t;       // even
            if (row0 < M)
                hu[((size_t)row0 * F_OUT + col) >> 1] =
                    pack_h2(acc[mt][nt][0], acc[mt][nt][1]);
            if (row8 < M)
                hu[((size_t)row8 * F_OUT + col) >> 1] =
                    pack_h2(acc[mt][nt][2], acc[mt][nt][3]);
        }
    }
}

// ---------------------------------------------------------------------------
// Kernel 3: CSR aggregation — unchanged from passing R10.
// ---------------------------------------------------------------------------
__global__ __launch_bounds__(256)
void aggregate_kernel(const __half* __restrict__ h16,
                      const float* __restrict__ bias,
                      float* __restrict__ out, int N) {
    const int warp = (blockIdx.x * blockDim.x + threadIdx.x) >> 5;
    const int lane = threadIdx.x & 31;
    const int half = lane >> 4;        // 0/1: which edge of the pair
    const int sub  = lane & 15;        // feature chunk: cols [sub*8, sub*8+8)
    if (warp >= N) return;

    const int s0 = g_off[warp];
    const int s1 = g_off[warp + 1];

    float acc[8];
    #pragma unroll
    for (int q = 0; q < 8; q++) acc[q] = 0.0f;

    for (int base = s0; base < s1; base += 32) {
        int s = 0; float v = 0.0f;
        if (base + lane < s1) {
            int2 e = g_edge[base + lane];
            s = e.x;
            v = __int_as_float(e.y);
        }
        const int cnt = min(32, s1 - base);
        #pragma unroll 4
        for (int j = 0; j < cnt; j += 2) {
            const int idx = j + half;                      // <= 31; v=0 pads
            int   ss = __shfl_sync(0xFFFFFFFFu, s, idx);
            float vv = __shfl_sync(0xFFFFFFFFu, v, idx);
            uint4 raw = ((const uint4*)(h16 + (size_t)ss * F_OUT))[sub];
            float2 f0 = __half22float2(*(const __half2*)&raw.x);
            float2 f1 = __half22float2(*(const __half2*)&raw.y);
            float2 f2 = __half22float2(*(const __half2*)&raw.z);
            float2 f3 = __half22float2(*(const __half2*)&raw.w);
            acc[0] += f0.x * vv; acc[1] += f0.y * vv;
            acc[2] += f1.x * vv; acc[3] += f1.y * vv;
            acc[4] += f2.x * vv; acc[5] += f2.y * vv;
            acc[6] += f3.x * vv; acc[7] += f3.y * vv;
        }
    }

    // combine the two edge-parity halves: lanes i and i+16 share columns
    #pragma unroll
    for (int q = 0; q < 8; q++)
        acc[q] += __shfl_xor_sync(0xFFFFFFFFu, acc[q], 16);

    if (half == 0) {
        const float4 b0 = ((const float4*)bias)[sub * 2];
        const float4 b1 = ((const float4*)bias)[sub * 2 + 1];
        float* op = out + (size_t)warp * F_OUT + sub * 8;
        *(float4*)op = make_float4(acc[0] + b0.x, acc[1] + b0.y,
                                   acc[2] + b0.z, acc[3] + b0.w);
        *(float4*)(op + 4) = make_float4(acc[4] + b1.x, acc[5] + b1.y,
                                         acc[6] + b1.z, acc[7] + b1.w);
    }
}

// ---------------------------------------------------------------------------
// Launch.  Inputs: x[f32], edge_src[i32], edge_dst[i32], edge_vals[f32],
//                  kernel[f32], bias[f32]
// CSR build (4 kernels) forked onto a side stream, overlapped with
// wsplit+GEMM; join before aggregate.
// ---------------------------------------------------------------------------
extern "C" void kernel_launch(void* const* d_in, const int* in_sizes, int n_in,
                              void* d_out, int out_size) {
    const float* x    = (const float*)d_in[0];
    const int*   esrc = (const int*)d_in[1];
    const int*   edst = (const int*)d_in[2];
    const float* eval = (const float*)d_in[3];
    const float* w    = (const float*)d_in[4];
    const float* bias = (const float*)d_in[5];
    float*       out  = (float*)d_out;

    const int M = in_sizes[0] / F_IN;     // 100000 nodes
    const int E = in_sizes[1];            // 1.6M edges

    __half *h16, *bh;
    cudaGetSymbolAddress((void**)&h16, g_h16);
    cudaGetSymbolAddress((void**)&bh,  g_Bh16);

    static cudaStream_t s2 = nullptr;
    static cudaEvent_t ev_fork = nullptr, ev_join = nullptr;
    static int init_done = 0;
    if (!init_done) {
        cudaStreamCreateWithFlags(&s2, cudaStreamNonBlocking);
        cudaEventCreateWithFlags(&ev_fork, cudaEventDisableTiming);
        cudaEventCreateWithFlags(&ev_join, cudaEventDisableTiming);
        cudaFuncSetAttribute(gemm_mma_kernel,
                             cudaFuncAttributeMaxDynamicSharedMemorySize,
                             GEMM_SMEM_BYTES);
        init_done = 1;
    }

    // ---- fork: CSR build on s2 ----
    cudaEventRecord(ev_fork, 0);
    cudaStreamWaitEvent(s2, ev_fork, 0);
    zero_cnt_kernel<<<(MAX_N + 255) / 256, 256, 0, s2>>>(MAX_N);
    count_kernel<<<(E + 255) / 256, 256, 0, s2>>>(edst, E);
    scan_fused_kernel<<<1, 1024, 0, s2>>>(E);
    fill_kernel<<<(E + 255) / 256, 256, 0, s2>>>(edst, esrc, eval, E);
    cudaEventRecord(ev_join, s2);

    // ---- main stream: dense path ----
    wsplit_kernel<<<F_IN, F_OUT>>>(w, bh);
    {
        int blocks = (M + 127) / 128;
        gemm_mma_kernel<<<blocks, 256, GEMM_SMEM_BYTES>>>(x, bh, h16, M);
    }

    // ---- join, then aggregate ----
    cudaStreamWaitEvent(0, ev_join, 0);
    {
        int blocks = (M * 32 + 255) / 256;   // 12500
        aggregate_kernel<<<blocks, 256>>>(h16, bias, out, M);
    }
}

// round 13
// speedup vs baseline: 1.9895x; 1.9895x over previous
#include <cuda_runtime.h>
#include <cuda_fp16.h>
#include <cstdint>

#define F_IN     256
#define F_OUT    128
#define MAX_N    100352            // 98 * 1024, covers 100000
#define MAX_E    1600000
#define SCAN_BLK 1024

// Static scratch — __device__ globals (no allocation allowed).
__device__ __half g_h16[(size_t)100000 * F_OUT];  // h = x @ W, fp16 (25.6 MB)
__device__ __half g_Bh16[F_IN * F_OUT];           // W^T fp16, [n][k]
__device__ int   g_cnt[MAX_N];
__device__ int   g_scan[MAX_N];
__device__ int   g_bsum[256];
__device__ int   g_off[MAX_N + 1];
__device__ int   g_cur[MAX_N];
__device__ int2  g_edge[MAX_E];                   // (src, val_bits) CSR order

// ---------------------------------------------------------------------------
// CSR build: zero -> count -> scanA -> scanB -> scanC -> fill  (R10 exact)
// ---------------------------------------------------------------------------
__global__ void zero_cnt_kernel(int n_pad) {
    int i = blockIdx.x * blockDim.x + threadIdx.x;
    if (i < n_pad) g_cnt[i] = 0;
}

__global__ void count_kernel(const int* __restrict__ edge_dst, int E) {
    int i = blockIdx.x * blockDim.x + threadIdx.x;
    if (i < E) atomicAdd(&g_cnt[edge_dst[i]], 1);
}

__global__ __launch_bounds__(SCAN_BLK)
void scanA_kernel() {
    __shared__ int s[SCAN_BLK];
    int t = threadIdx.x;
    int i = blockIdx.x * SCAN_BLK + t;
    int v = g_cnt[i];
    s[t] = v;
    __syncthreads();
    #pragma unroll
    for (int off = 1; off < SCAN_BLK; off <<= 1) {
        int tmp = (t >= off) ? s[t - off] : 0;
        __syncthreads();
        s[t] += tmp;
        __syncthreads();
    }
    g_scan[i] = s[t] - v;
    if (t == SCAN_BLK - 1) g_bsum[blockIdx.x] = s[t];
}

__global__ __launch_bounds__(256)
void scanB_kernel(int nblk) {
    __shared__ int s[256];
    int t = threadIdx.x;
    int v = (t < nblk) ? g_bsum[t] : 0;
    s[t] = v;
    __syncthreads();
    #pragma unroll
    for (int off = 1; off < 256; off <<= 1) {
        int tmp = (t >= off) ? s[t - off] : 0;
        __syncthreads();
        s[t] += tmp;
        __syncthreads();
    }
    g_bsum[t] = s[t] - v;
}

__global__ void scanC_kernel(int N, int E) {
    int i = blockIdx.x * blockDim.x + threadIdx.x;
    if (i <= N) {
        int o = (i == N) ? E : (g_scan[i] + g_bsum[i / SCAN_BLK]);
        g_off[i] = o;
        if (i < N) g_cur[i] = o;
    }
}

__global__ void fill_kernel(const int* __restrict__ edge_dst,
                            const int* __restrict__ edge_src,
                            const float* __restrict__ edge_vals, int E) {
    int i = blockIdx.x * blockDim.x + threadIdx.x;
    if (i < E) {
        int p = atomicAdd(&g_cur[edge_dst[i]], 1);
        g_edge[p] = make_int2(edge_src[i], __float_as_int(edge_vals[i]));
    }
}

// ---------------------------------------------------------------------------
// Kernel 2a: W transpose to fp16:  Bh[n][k] = fp16(w[k][n])
// ---------------------------------------------------------------------------
__global__ void wsplit_kernel(const float* __restrict__ w,
                              __half* __restrict__ bh) {
    int k = blockIdx.x;        // 0..255
    int n = threadIdx.x;       // 0..127
    bh[n * F_IN + k] = __float2half_rn(w[k * F_OUT + n]);
}

// ---------------------------------------------------------------------------
// Kernel 2b: mma.sync fp16 GEMM (single pass) — unchanged from passing R10.
// ---------------------------------------------------------------------------
#define KC       32
#define NCHUNK   (F_IN / KC)       // 8
#define ASU      20                // u32 per SMEM row (16 data + 4 pad)
#define SM_A     0
#define SM_BH    (128 * ASU)
#define GEMM_SMEM_BYTES (2 * 128 * ASU * 4)   // 20480

__device__ __forceinline__ uint32_t pack_h2(float a, float b) {
    __half2 t = __floats2half2_rn(a, b);   // .x = a (low half)
    return *(uint32_t*)&t;
}

__device__ __forceinline__ void mma_f16(float* d, const uint32_t* a,
                                        const uint32_t* b) {
    asm volatile(
        "mma.sync.aligned.m16n8k16.row.col.f32.f16.f16.f32 "
        "{%0, %1, %2, %3}, {%4, %5, %6, %7}, {%8, %9}, {%0, %1, %2, %3};"
        : "+f"(d[0]), "+f"(d[1]), "+f"(d[2]), "+f"(d[3])
        : "r"(a[0]), "r"(a[1]), "r"(a[2]), "r"(a[3]), "r"(b[0]), "r"(b[1]));
}

__global__ __launch_bounds__(256, 2)
void gemm_mma_kernel(const float* __restrict__ x,
                     const __half* __restrict__ bh_g,
                     __half* __restrict__ h16, int M) {
    extern __shared__ uint32_t smu[];
    const int tid  = threadIdx.x;
    const int wid  = tid >> 5;
    const int lane = tid & 31;
    const int g = lane >> 2;
    const int t = lane & 3;
    const int wm = wid & 3;
    const int wn = wid >> 2;
    const int block_row = blockIdx.x * 128;

    const uint32_t* bhu = (const uint32_t*)bh_g;   // [n][128] u32 rows
    uint32_t* hu = (uint32_t*)h16;                 // h as u32 (half2) words

    float acc[2][8][4];
    #pragma unroll
    for (int i = 0; i < 2; i++)
        #pragma unroll
        for (int j = 0; j < 8; j++)
            #pragma unroll
            for (int q = 0; q < 4; q++) acc[i][j][q] = 0.0f;

    for (int c = 0; c < NCHUNK; c++) {
        if (c > 0) __syncthreads();
        // ---- A: 128 rows x 32 k; fp32 -> fp16, packed u32 pairs ----
        #pragma unroll
        for (int i = 0; i < 4; i++) {
            int fidx = i * 256 + tid;          // 1024 float4 slots
            int row = fidx >> 3, c4 = fidx & 7;
            int grow = block_row + row;
            float4 v = make_float4(0.f, 0.f, 0.f, 0.f);
            if (grow < M)
                v = *(const float4*)(x + (size_t)grow * F_IN + c * KC + c4 * 4);
            uint32_t base = row * ASU + c4 * 2;
            *(uint2*)&smu[SM_A + base] =
                make_uint2(pack_h2(v.x, v.y), pack_h2(v.z, v.w));
        }
        // ---- B: 128 n-rows x 32 k (fp16 in gmem) ----
        {
            int fidx = tid;                    // 256 uint4 slots
            int row = fidx >> 1, q = fidx & 1;
            const size_t go = (size_t)row * (F_IN / 2) + c * (KC / 2) + q * 8;
            uint4 vh0 = *(const uint4*)(bhu + go);
            uint4 vh1 = *(const uint4*)(bhu + go + 4);
            uint32_t base = row * ASU + q * 8;
            *(uint4*)&smu[SM_BH + base] = vh0;
            *(uint4*)&smu[SM_BH + base + 4] = vh1;
        }
        __syncthreads();

        #pragma unroll
        for (int kp = 0; kp < KC / 2; kp += 8) {   // two k16 steps
            uint32_t a[2][4];
            #pragma unroll
            for (int mt = 0; mt < 2; mt++) {
                int r0 = (wm * 32 + mt * 16 + g) * ASU + kp + t;
                int r8 = (wm * 32 + mt * 16 + g + 8) * ASU + kp + t;
                a[mt][0] = smu[SM_A + r0];
                a[mt][1] = smu[SM_A + r8];
                a[mt][2] = smu[SM_A + r0 + 4];
                a[mt][3] = smu[SM_A + r8 + 4];
            }
            #pragma unroll
            for (int nt = 0; nt < 8; nt++) {
                int nrow = (wn * 64 + nt * 8 + g) * ASU + kp + t;
                uint32_t bh[2];
                bh[0] = smu[SM_BH + nrow];
                bh[1] = smu[SM_BH + nrow + 4];
                #pragma unroll
                for (int mt = 0; mt < 2; mt++)
                    mma_f16(acc[mt][nt], a[mt], bh);
            }
        }
    }

    // ---- writeback h as fp16 (one u32 = half2 per fragment pair) ----
    #pragma unroll
    for (int mt = 0; mt < 2; mt++) {
        int row0 = block_row + wm * 32 + mt * 16 + g;
        int row8 = row0 + 8;
        #pragma unroll
        for (int nt = 0; nt < 8; nt++) {
            int col = wn * 64 + nt * 8 + 2 * t;       // even
            if (row0 < M)
                hu[((size_t)row0 * F_OUT + col) >> 1] =
                    pack_h2(acc[mt][nt][0], acc[mt][nt][1]);
            if (row8 < M)
                hu[((size_t)row8 * F_OUT + col) >> 1] =
                    pack_h2(acc[mt][nt][2], acc[mt][nt][3]);
        }
    }
}

// ---------------------------------------------------------------------------
// Kernel 3: CSR aggregation — TWO warps per dst node (64 cols each),
// 16 lanes per edge (uint2 = 4 halves), 2 edges per step; fp32 accumulation.
// ---------------------------------------------------------------------------
__global__ __launch_bounds__(256)
void aggregate_kernel(const __half* __restrict__ h16,
                      const float* __restrict__ bias,
                      float* __restrict__ out, int N) {
    const int gwarp = (blockIdx.x * blockDim.x + threadIdx.x) >> 5;
    const int node = gwarp >> 1;       // node index
    const int wh   = gwarp & 1;        // feature half: cols [wh*64, wh*64+64)
    const int lane = threadIdx.x & 31;
    const int half = lane >> 4;        // 0/1: which edge of the pair
    const int sub  = lane & 15;        // 4-col chunk: cols wh*64 + sub*4
    if (node >= N) return;

    const int s0 = g_off[node];
    const int s1 = g_off[node + 1];

    float acc[4];
    #pragma unroll
    for (int q = 0; q < 4; q++) acc[q] = 0.0f;

    const __half* hbase = h16 + wh * 64;

    for (int base = s0; base < s1; base += 32) {
        int s = 0; float v = 0.0f;
        if (base + lane < s1) {
            int2 e = g_edge[base + lane];
            s = e.x;
            v = __int_as_float(e.y);
        }
        const int cnt = min(32, s1 - base);
        #pragma unroll 4
        for (int j = 0; j < cnt; j += 2) {
            const int idx = j + half;                      // <= 31; v=0 pads
            int   ss = __shfl_sync(0xFFFFFFFFu, s, idx);
            float vv = __shfl_sync(0xFFFFFFFFu, v, idx);
            uint2 raw = ((const uint2*)(hbase + (size_t)ss * F_OUT))[sub];
            float2 f0 = __half22float2(*(const __half2*)&raw.x);
            float2 f1 = __half22float2(*(const __half2*)&raw.y);
            acc[0] += f0.x * vv; acc[1] += f0.y * vv;
            acc[2] += f1.x * vv; acc[3] += f1.y * vv;
        }
    }

    // combine the two edge-parity halves: lanes i and i+16 share columns
    #pragma unroll
    for (int q = 0; q < 4; q++)
        acc[q] += __shfl_xor_sync(0xFFFFFFFFu, acc[q], 16);

    if (half == 0) {
        const float4 b = ((const float4*)bias)[wh * 16 + sub];
        *(float4*)(out + (size_t)node * F_OUT + wh * 64 + sub * 4) =
            make_float4(acc[0] + b.x, acc[1] + b.y,
                        acc[2] + b.z, acc[3] + b.w);
    }
}

// ---------------------------------------------------------------------------
// Launch.  Inputs: x[f32], edge_src[i32], edge_dst[i32], edge_vals[f32],
//                  kernel[f32], bias[f32]
// CSR build forked onto a side stream, overlapped with wsplit+GEMM.
// ---------------------------------------------------------------------------
extern "C" void kernel_launch(void* const* d_in, const int* in_sizes, int n_in,
                              void* d_out, int out_size) {
    const float* x    = (const float*)d_in[0];
    const int*   esrc = (const int*)d_in[1];
    const int*   edst = (const int*)d_in[2];
    const float* eval = (const float*)d_in[3];
    const float* w    = (const float*)d_in[4];
    const float* bias = (const float*)d_in[5];
    float*       out  = (float*)d_out;

    const int M = in_sizes[0] / F_IN;     // 100000 nodes
    const int E = in_sizes[1];            // 1.6M edges
    const int n_pad  = ((M + SCAN_BLK - 1) / SCAN_BLK) * SCAN_BLK;
    const int n_sblk = n_pad / SCAN_BLK;  // 98

    __half *h16, *bh;
    cudaGetSymbolAddress((void**)&h16, g_h16);
    cudaGetSymbolAddress((void**)&bh,  g_Bh16);

    static cudaStream_t s2 = nullptr;
    static cudaEvent_t ev_fork = nullptr, ev_join = nullptr;
    static int init_done = 0;
    if (!init_done) {
        cudaStreamCreateWithFlags(&s2, cudaStreamNonBlocking);
        cudaEventCreateWithFlags(&ev_fork, cudaEventDisableTiming);
        cudaEventCreateWithFlags(&ev_join, cudaEventDisableTiming);
        cudaFuncSetAttribute(gemm_mma_kernel,
                             cudaFuncAttributeMaxDynamicSharedMemorySize,
                             GEMM_SMEM_BYTES);
        init_done = 1;
    }

    // ---- fork: CSR build on s2 ----
    cudaEventRecord(ev_fork, 0);
    cudaStreamWaitEvent(s2, ev_fork, 0);
    zero_cnt_kernel<<<(n_pad + 255) / 256, 256, 0, s2>>>(n_pad);
    count_kernel<<<(E + 255) / 256, 256, 0, s2>>>(edst, E);
    scanA_kernel<<<n_sblk, SCAN_BLK, 0, s2>>>();
    scanB_kernel<<<1, 256, 0, s2>>>(n_sblk);
    scanC_kernel<<<(M + 256) / 256, 256, 0, s2>>>(M, E);
    fill_kernel<<<(E + 255) / 256, 256, 0, s2>>>(edst, esrc, eval, E);
    cudaEventRecord(ev_join, s2);

    // ---- main stream: dense path ----
    wsplit_kernel<<<F_IN, F_OUT>>>(w, bh);
    {
        int blocks = (M + 127) / 128;
        gemm_mma_kernel<<<blocks, 256, GEMM_SMEM_BYTES>>>(x, bh, h16, M);
    }

    // ---- join, then aggregate ----
    cudaStreamWaitEvent(0, ev_join, 0);
    {
        long long warps = 2LL * M;           // 2 warps per node
        int blocks = (int)((warps * 32 + 255) / 256);   // 25000
        aggregate_kernel<<<blocks, 256>>>(h16, bias, out, M);
    }
}

// round 14
// speedup vs baseline: 2.2757x; 1.1439x over previous
#include <cuda_runtime.h>
#include <cuda_fp16.h>
#include <cstdint>

#define F_IN     256
#define F_OUT    128
#define MAX_N    100352            // 98 * 1024, covers 100000
#define MAX_E    1600000
#define SCAN_BLK 1024

// Static scratch — __device__ globals (no allocation allowed).
__device__ __half g_h16[(size_t)100000 * F_OUT];  // h = x @ W, fp16 (25.6 MB)
__device__ __half g_Bh16[F_IN * F_OUT];           // W^T fp16, [n][k]
__device__ int   g_cnt[MAX_N];
__device__ int   g_scan[MAX_N];
__device__ int   g_bsum[256];
__device__ int   g_off[MAX_N + 1];
__device__ int   g_cur[MAX_N];
__device__ int2  g_edge[MAX_E];                   // (src, val_bits) CSR order

// ---------------------------------------------------------------------------
// CSR build: zero -> count(x4) -> scanA -> scanB -> scanC -> fill(x4)
// count/fill: 4 edges per thread -> 4 independent ATOMGs in flight (MLP 4).
// ---------------------------------------------------------------------------
__global__ void zero_cnt_kernel(int n_pad) {
    int i = blockIdx.x * blockDim.x + threadIdx.x;
    if (i < n_pad) g_cnt[i] = 0;
}

__global__ void count_kernel(const int* __restrict__ edge_dst, int E) {
    int i = (blockIdx.x * blockDim.x + threadIdx.x) * 4;
    if (i + 3 < E) {
        int4 d = *(const int4*)(edge_dst + i);
        atomicAdd(&g_cnt[d.x], 1);
        atomicAdd(&g_cnt[d.y], 1);
        atomicAdd(&g_cnt[d.z], 1);
        atomicAdd(&g_cnt[d.w], 1);
    } else {
        for (int k = i; k < E; k++) atomicAdd(&g_cnt[edge_dst[k]], 1);
    }
}

__global__ __launch_bounds__(SCAN_BLK)
void scanA_kernel() {
    __shared__ int s[SCAN_BLK];
    int t = threadIdx.x;
    int i = blockIdx.x * SCAN_BLK + t;
    int v = g_cnt[i];
    s[t] = v;
    __syncthreads();
    #pragma unroll
    for (int off = 1; off < SCAN_BLK; off <<= 1) {
        int tmp = (t >= off) ? s[t - off] : 0;
        __syncthreads();
        s[t] += tmp;
        __syncthreads();
    }
    g_scan[i] = s[t] - v;
    if (t == SCAN_BLK - 1) g_bsum[blockIdx.x] = s[t];
}

__global__ __launch_bounds__(256)
void scanB_kernel(int nblk) {
    __shared__ int s[256];
    int t = threadIdx.x;
    int v = (t < nblk) ? g_bsum[t] : 0;
    s[t] = v;
    __syncthreads();
    #pragma unroll
    for (int off = 1; off < 256; off <<= 1) {
        int tmp = (t >= off) ? s[t - off] : 0;
        __syncthreads();
        s[t] += tmp;
        __syncthreads();
    }
    g_bsum[t] = s[t] - v;
}

__global__ void scanC_kernel(int N, int E) {
    int i = blockIdx.x * blockDim.x + threadIdx.x;
    if (i <= N) {
        int o = (i == N) ? E : (g_scan[i] + g_bsum[i / SCAN_BLK]);
        g_off[i] = o;
        if (i < N) g_cur[i] = o;
    }
}

__global__ void fill_kernel(const int* __restrict__ edge_dst,
                            const int* __restrict__ edge_src,
                            const float* __restrict__ edge_vals, int E) {
    int i = (blockIdx.x * blockDim.x + threadIdx.x) * 4;
    if (i + 3 < E) {
        int4   d = *(const int4*)(edge_dst + i);
        int4   s = *(const int4*)(edge_src + i);
        float4 v = *(const float4*)(edge_vals + i);
        int p0 = atomicAdd(&g_cur[d.x], 1);
        int p1 = atomicAdd(&g_cur[d.y], 1);
        int p2 = atomicAdd(&g_cur[d.z], 1);
        int p3 = atomicAdd(&g_cur[d.w], 1);
        g_edge[p0] = make_int2(s.x, __float_as_int(v.x));
        g_edge[p1] = make_int2(s.y, __float_as_int(v.y));
        g_edge[p2] = make_int2(s.z, __float_as_int(v.z));
        g_edge[p3] = make_int2(s.w, __float_as_int(v.w));
    } else {
        for (int k = i; k < E; k++) {
            int p = atomicAdd(&g_cur[edge_dst[k]], 1);
            g_edge[p] = make_int2(edge_src[k], __float_as_int(edge_vals[k]));
        }
    }
}

// ---------------------------------------------------------------------------
// Kernel 2a: W transpose to fp16:  Bh[n][k] = fp16(w[k][n])
// ---------------------------------------------------------------------------
__global__ void wsplit_kernel(const float* __restrict__ w,
                              __half* __restrict__ bh) {
    int k = blockIdx.x;        // 0..255
    int n = threadIdx.x;       // 0..127
    bh[n * F_IN + k] = __float2half_rn(w[k * F_OUT + n]);
}

// ---------------------------------------------------------------------------
// Kernel 2b: mma.sync fp16 GEMM (single pass) — unchanged from passing R10.
// ---------------------------------------------------------------------------
#define KC       32
#define NCHUNK   (F_IN / KC)       // 8
#define ASU      20                // u32 per SMEM row (16 data + 4 pad)
#define SM_A     0
#define SM_BH    (128 * ASU)
#define GEMM_SMEM_BYTES (2 * 128 * ASU * 4)   // 20480

__device__ __forceinline__ uint32_t pack_h2(float a, float b) {
    __half2 t = __floats2half2_rn(a, b);   // .x = a (low half)
    return *(uint32_t*)&t;
}

__device__ __forceinline__ void mma_f16(float* d, const uint32_t* a,
                                        const uint32_t* b) {
    asm volatile(
        "mma.sync.aligned.m16n8k16.row.col.f32.f16.f16.f32 "
        "{%0, %1, %2, %3}, {%4, %5, %6, %7}, {%8, %9}, {%0, %1, %2, %3};"
        : "+f"(d[0]), "+f"(d[1]), "+f"(d[2]), "+f"(d[3])
        : "r"(a[0]), "r"(a[1]), "r"(a[2]), "r"(a[3]), "r"(b[0]), "r"(b[1]));
}

__global__ __launch_bounds__(256, 2)
void gemm_mma_kernel(const float* __restrict__ x,
                     const __half* __restrict__ bh_g,
                     __half* __restrict__ h16, int M) {
    extern __shared__ uint32_t smu[];
    const int tid  = threadIdx.x;
    const int wid  = tid >> 5;
    const int lane = tid & 31;
    const int g = lane >> 2;
    const int t = lane & 3;
    const int wm = wid & 3;
    const int wn = wid >> 2;
    const int block_row = blockIdx.x * 128;

    const uint32_t* bhu = (const uint32_t*)bh_g;   // [n][128] u32 rows
    uint32_t* hu = (uint32_t*)h16;                 // h as u32 (half2) words

    float acc[2][8][4];
    #pragma unroll
    for (int i = 0; i < 2; i++)
        #pragma unroll
        for (int j = 0; j < 8; j++)
            #pragma unroll
            for (int q = 0; q < 4; q++) acc[i][j][q] = 0.0f;

    for (int c = 0; c < NCHUNK; c++) {
        if (c > 0) __syncthreads();
        // ---- A: 128 rows x 32 k; fp32 -> fp16, packed u32 pairs ----
        #pragma unroll
        for (int i = 0; i < 4; i++) {
            int fidx = i * 256 + tid;          // 1024 float4 slots
            int row = fidx >> 3, c4 = fidx & 7;
            int grow = block_row + row;
            float4 v = make_float4(0.f, 0.f, 0.f, 0.f);
            if (grow < M)
                v = *(const float4*)(x + (size_t)grow * F_IN + c * KC + c4 * 4);
            uint32_t base = row * ASU + c4 * 2;
            *(uint2*)&smu[SM_A + base] =
                make_uint2(pack_h2(v.x, v.y), pack_h2(v.z, v.w));
        }
        // ---- B: 128 n-rows x 32 k (fp16 in gmem) ----
        {
            int fidx = tid;                    // 256 uint4 slots
            int row = fidx >> 1, q = fidx & 1;
            const size_t go = (size_t)row * (F_IN / 2) + c * (KC / 2) + q * 8;
            uint4 vh0 = *(const uint4*)(bhu + go);
            uint4 vh1 = *(const uint4*)(bhu + go + 4);
            uint32_t base = row * ASU + q * 8;
            *(uint4*)&smu[SM_BH + base] = vh0;
            *(uint4*)&smu[SM_BH + base + 4] = vh1;
        }
        __syncthreads();

        #pragma unroll
        for (int kp = 0; kp < KC / 2; kp += 8) {   // two k16 steps
            uint32_t a[2][4];
            #pragma unroll
            for (int mt = 0; mt < 2; mt++) {
                int r0 = (wm * 32 + mt * 16 + g) * ASU + kp + t;
                int r8 = (wm * 32 + mt * 16 + g + 8) * ASU + kp + t;
                a[mt][0] = smu[SM_A + r0];
                a[mt][1] = smu[SM_A + r8];
                a[mt][2] = smu[SM_A + r0 + 4];
                a[mt][3] = smu[SM_A + r8 + 4];
            }
            #pragma unroll
            for (int nt = 0; nt < 8; nt++) {
                int nrow = (wn * 64 + nt * 8 + g) * ASU + kp + t;
                uint32_t bh[2];
                bh[0] = smu[SM_BH + nrow];
                bh[1] = smu[SM_BH + nrow + 4];
                #pragma unroll
                for (int mt = 0; mt < 2; mt++)
                    mma_f16(acc[mt][nt], a[mt], bh);
            }
        }
    }

    // ---- writeback h as fp16 (one u32 = half2 per fragment pair) ----
    #pragma unroll
    for (int mt = 0; mt < 2; mt++) {
        int row0 = block_row + wm * 32 + mt * 16 + g;
        int row8 = row0 + 8;
        #pragma unroll
        for (int nt = 0; nt < 8; nt++) {
            int col = wn * 64 + nt * 8 + 2 * t;       // even
            if (row0 < M)
                hu[((size_t)row0 * F_OUT + col) >> 1] =
                    pack_h2(acc[mt][nt][0], acc[mt][nt][1]);
            if (row8 < M)
                hu[((size_t)row8 * F_OUT + col) >> 1] =
                    pack_h2(acc[mt][nt][2], acc[mt][nt][3]);
        }
    }
}

// ---------------------------------------------------------------------------
// Kernel 3: CSR aggregation — EXACT R10 version (one warp per node,
// 16 lanes per edge, uint4 per lane, 2 edges per step; fp32 accum).
// ---------------------------------------------------------------------------
__global__ __launch_bounds__(256)
void aggregate_kernel(const __half* __restrict__ h16,
                      const float* __restrict__ bias,
                      float* __restrict__ out, int N) {
    const int warp = (blockIdx.x * blockDim.x + threadIdx.x) >> 5;
    const int lane = threadIdx.x & 31;
    const int half = lane >> 4;        // 0/1: which edge of the pair
    const int sub  = lane & 15;        // feature chunk: cols [sub*8, sub*8+8)
    if (warp >= N) return;

    const int s0 = g_off[warp];
    const int s1 = g_off[warp + 1];

    float acc[8];
    #pragma unroll
    for (int q = 0; q < 8; q++) acc[q] = 0.0f;

    for (int base = s0; base < s1; base += 32) {
        int s = 0; float v = 0.0f;
        if (base + lane < s1) {
            int2 e = g_edge[base + lane];
            s = e.x;
            v = __int_as_float(e.y);
        }
        const int cnt = min(32, s1 - base);
        #pragma unroll 4
        for (int j = 0; j < cnt; j += 2) {
            const int idx = j + half;                      // <= 31; v=0 pads
            int   ss = __shfl_sync(0xFFFFFFFFu, s, idx);
            float vv = __shfl_sync(0xFFFFFFFFu, v, idx);
            uint4 raw = ((const uint4*)(h16 + (size_t)ss * F_OUT))[sub];
            float2 f0 = __half22float2(*(const __half2*)&raw.x);
            float2 f1 = __half22float2(*(const __half2*)&raw.y);
            float2 f2 = __half22float2(*(const __half2*)&raw.z);
            float2 f3 = __half22float2(*(const __half2*)&raw.w);
            acc[0] += f0.x * vv; acc[1] += f0.y * vv;
            acc[2] += f1.x * vv; acc[3] += f1.y * vv;
            acc[4] += f2.x * vv; acc[5] += f2.y * vv;
            acc[6] += f3.x * vv; acc[7] += f3.y * vv;
        }
    }

    // combine the two edge-parity halves: lanes i and i+16 share columns
    #pragma unroll
    for (int q = 0; q < 8; q++)
        acc[q] += __shfl_xor_sync(0xFFFFFFFFu, acc[q], 16);

    if (half == 0) {
        const float4 b0 = ((const float4*)bias)[sub * 2];
        const float4 b1 = ((const float4*)bias)[sub * 2 + 1];
        float* op = out + (size_t)warp * F_OUT + sub * 8;
        *(float4*)op = make_float4(acc[0] + b0.x, acc[1] + b0.y,
                                   acc[2] + b0.z, acc[3] + b0.w);
        *(float4*)(op + 4) = make_float4(acc[4] + b1.x, acc[5] + b1.y,
                                         acc[6] + b1.z, acc[7] + b1.w);
    }
}

// ---------------------------------------------------------------------------
// Launch.  Inputs: x[f32], edge_src[i32], edge_dst[i32], edge_vals[f32],
//                  kernel[f32], bias[f32]
// CSR build forked onto a side stream, overlapped with wsplit+GEMM.
// ---------------------------------------------------------------------------
extern "C" void kernel_launch(void* const* d_in, const int* in_sizes, int n_in,
                              void* d_out, int out_size) {
    const float* x    = (const float*)d_in[0];
    const int*   esrc = (const int*)d_in[1];
    const int*   edst = (const int*)d_in[2];
    const float* eval = (const float*)d_in[3];
    const float* w    = (const float*)d_in[4];
    const float* bias = (const float*)d_in[5];
    float*       out  = (float*)d_out;

    const int M = in_sizes[0] / F_IN;     // 100000 nodes
    const int E = in_sizes[1];            // 1.6M edges
    const int n_pad  = ((M + SCAN_BLK - 1) / SCAN_BLK) * SCAN_BLK;
    const int n_sblk = n_pad / SCAN_BLK;  // 98

    __half *h16, *bh;
    cudaGetSymbolAddress((void**)&h16, g_h16);
    cudaGetSymbolAddress((void**)&bh,  g_Bh16);

    static cudaStream_t s2 = nullptr;
    static cudaEvent_t ev_fork = nullptr, ev_join = nullptr;
    static int init_done = 0;
    if (!init_done) {
        cudaStreamCreateWithFlags(&s2, cudaStreamNonBlocking);
        cudaEventCreateWithFlags(&ev_fork, cudaEventDisableTiming);
        cudaEventCreateWithFlags(&ev_join, cudaEventDisableTiming);
        cudaFuncSetAttribute(gemm_mma_kernel,
                             cudaFuncAttributeMaxDynamicSharedMemorySize,
                             GEMM_SMEM_BYTES);
        init_done = 1;
    }

    // ---- fork: CSR build on s2 ----
    cudaEventRecord(ev_fork, 0);
    cudaStreamWaitEvent(s2, ev_fork, 0);
    zero_cnt_kernel<<<(n_pad + 255) / 256, 256, 0, s2>>>(n_pad);
    count_kernel<<<(E / 4 + 255) / 256, 256, 0, s2>>>(edst, E);
    scanA_kernel<<<n_sblk, SCAN_BLK, 0, s2>>>();
    scanB_kernel<<<1, 256, 0, s2>>>(n_sblk);
    scanC_kernel<<<(M + 256) / 256, 256, 0, s2>>>(M, E);
    fill_kernel<<<(E / 4 + 255) / 256, 256, 0, s2>>>(edst, esrc, eval, E);
    cudaEventRecord(ev_join, s2);

    // ---- main stream: dense path ----
    wsplit_kernel<<<F_IN, F_OUT>>>(w, bh);
    {
        int blocks = (M + 127) / 128;
        gemm_mma_kernel<<<blocks, 256, GEMM_SMEM_BYTES>>>(x, bh, h16, M);
    }

    // ---- join, then aggregate ----
    cudaStreamWaitEvent(0, ev_join, 0);
    {
        int blocks = (M * 32 + 255) / 256;   // 12500
        aggregate_kernel<<<blocks, 256>>>(h16, bias, out, M);
    }
}

// round 15
// speedup vs baseline: 2.3800x; 1.0458x over previous
#include <cuda_runtime.h>
#include <cuda_fp16.h>
#include <cstdint>

#define F_IN     256
#define F_OUT    128
#define MAX_N    100352            // 98 * 1024, covers 100000
#define MAX_E    1600000
#define SCAN_BLK 1024

// Static scratch — __device__ globals (no allocation allowed).
__device__ __half g_h16[(size_t)100000 * F_OUT];  // h = x @ W, fp16 (25.6 MB)
__device__ __half g_Bh16[F_IN * F_OUT];           // W^T fp16, [n][k]
__device__ int   g_cnt[MAX_N];
__device__ int   g_scan[MAX_N];
__device__ int   g_bsum[256];
__device__ int   g_off[MAX_N + 1];
__device__ int   g_cur[MAX_N];
__device__ int2  g_edge[MAX_E];                   // (src, val_bits) CSR order

// ---------------------------------------------------------------------------
// CSR build: zero -> count(x4) -> scanA -> scanB -> scanC -> fill(x4)
// ---------------------------------------------------------------------------
__global__ void zero_cnt_kernel(int n_pad) {
    int i = blockIdx.x * blockDim.x + threadIdx.x;
    if (i < n_pad) g_cnt[i] = 0;
}

__global__ void count_kernel(const int* __restrict__ edge_dst, int E) {
    int i = (blockIdx.x * blockDim.x + threadIdx.x) * 4;
    if (i + 3 < E) {
        int4 d = *(const int4*)(edge_dst + i);
        atomicAdd(&g_cnt[d.x], 1);
        atomicAdd(&g_cnt[d.y], 1);
        atomicAdd(&g_cnt[d.z], 1);
        atomicAdd(&g_cnt[d.w], 1);
    } else {
        for (int k = i; k < E; k++) atomicAdd(&g_cnt[edge_dst[k]], 1);
    }
}

__global__ __launch_bounds__(SCAN_BLK)
void scanA_kernel() {
    __shared__ int s[SCAN_BLK];
    int t = threadIdx.x;
    int i = blockIdx.x * SCAN_BLK + t;
    int v = g_cnt[i];
    s[t] = v;
    __syncthreads();
    #pragma unroll
    for (int off = 1; off < SCAN_BLK; off <<= 1) {
        int tmp = (t >= off) ? s[t - off] : 0;
        __syncthreads();
        s[t] += tmp;
        __syncthreads();
    }
    g_scan[i] = s[t] - v;
    if (t == SCAN_BLK - 1) g_bsum[blockIdx.x] = s[t];
}

__global__ __launch_bounds__(256)
void scanB_kernel(int nblk) {
    __shared__ int s[256];
    int t = threadIdx.x;
    int v = (t < nblk) ? g_bsum[t] : 0;
    s[t] = v;
    __syncthreads();
    #pragma unroll
    for (int off = 1; off < 256; off <<= 1) {
        int tmp = (t >= off) ? s[t - off] : 0;
        __syncthreads();
        s[t] += tmp;
        __syncthreads();
    }
    g_bsum[t] = s[t] - v;
}

__global__ void scanC_kernel(int N, int E) {
    int i = blockIdx.x * blockDim.x + threadIdx.x;
    if (i <= N) {
        int o = (i == N) ? E : (g_scan[i] + g_bsum[i / SCAN_BLK]);
        g_off[i] = o;
        if (i < N) g_cur[i] = o;
    }
}

__global__ void fill_kernel(const int* __restrict__ edge_dst,
                            const int* __restrict__ edge_src,
                            const float* __restrict__ edge_vals, int E) {
    int i = (blockIdx.x * blockDim.x + threadIdx.x) * 4;
    if (i + 3 < E) {
        int4   d = *(const int4*)(edge_dst + i);
        int4   s = *(const int4*)(edge_src + i);
        float4 v = *(const float4*)(edge_vals + i);
        int p0 = atomicAdd(&g_cur[d.x], 1);
        int p1 = atomicAdd(&g_cur[d.y], 1);
        int p2 = atomicAdd(&g_cur[d.z], 1);
        int p3 = atomicAdd(&g_cur[d.w], 1);
        g_edge[p0] = make_int2(s.x, __float_as_int(v.x));
        g_edge[p1] = make_int2(s.y, __float_as_int(v.y));
        g_edge[p2] = make_int2(s.z, __float_as_int(v.z));
        g_edge[p3] = make_int2(s.w, __float_as_int(v.w));
    } else {
        for (int k = i; k < E; k++) {
            int p = atomicAdd(&g_cur[edge_dst[k]], 1);
            g_edge[p] = make_int2(edge_src[k], __float_as_int(edge_vals[k]));
        }
    }
}

// ---------------------------------------------------------------------------
// Kernel 2a: W transpose to fp16:  Bh[n][k] = fp16(w[k][n])
// ---------------------------------------------------------------------------
__global__ void wsplit_kernel(const float* __restrict__ w,
                              __half* __restrict__ bh) {
    int k = blockIdx.x;        // 0..255
    int n = threadIdx.x;       // 0..127
    bh[n * F_IN + k] = __float2half_rn(w[k * F_OUT + n]);
}

// ---------------------------------------------------------------------------
// Kernel 2b: mma.sync fp16 GEMM (single pass) — unchanged from passing R10.
// ---------------------------------------------------------------------------
#define KC       32
#define NCHUNK   (F_IN / KC)       // 8
#define ASU      20                // u32 per SMEM row (16 data + 4 pad)
#define SM_A     0
#define SM_BH    (128 * ASU)
#define GEMM_SMEM_BYTES (2 * 128 * ASU * 4)   // 20480

__device__ __forceinline__ uint32_t pack_h2(float a, float b) {
    __half2 t = __floats2half2_rn(a, b);   // .x = a (low half)
    return *(uint32_t*)&t;
}

__device__ __forceinline__ void mma_f16(float* d, const uint32_t* a,
                                        const uint32_t* b) {
    asm volatile(
        "mma.sync.aligned.m16n8k16.row.col.f32.f16.f16.f32 "
        "{%0, %1, %2, %3}, {%4, %5, %6, %7}, {%8, %9}, {%0, %1, %2, %3};"
        : "+f"(d[0]), "+f"(d[1]), "+f"(d[2]), "+f"(d[3])
        : "r"(a[0]), "r"(a[1]), "r"(a[2]), "r"(a[3]), "r"(b[0]), "r"(b[1]));
}

__global__ __launch_bounds__(256, 2)
void gemm_mma_kernel(const float* __restrict__ x,
                     const __half* __restrict__ bh_g,
                     __half* __restrict__ h16, int M) {
    extern __shared__ uint32_t smu[];
    const int tid  = threadIdx.x;
    const int wid  = tid >> 5;
    const int lane = tid & 31;
    const int g = lane >> 2;
    const int t = lane & 3;
    const int wm = wid & 3;
    const int wn = wid >> 2;
    const int block_row = blockIdx.x * 128;

    const uint32_t* bhu = (const uint32_t*)bh_g;   // [n][128] u32 rows
    uint32_t* hu = (uint32_t*)h16;                 // h as u32 (half2) words

    float acc[2][8][4];
    #pragma unroll
    for (int i = 0; i < 2; i++)
        #pragma unroll
        for (int j = 0; j < 8; j++)
            #pragma unroll
            for (int q = 0; q < 4; q++) acc[i][j][q] = 0.0f;

    for (int c = 0; c < NCHUNK; c++) {
        if (c > 0) __syncthreads();
        // ---- A: 128 rows x 32 k; fp32 -> fp16, packed u32 pairs ----
        #pragma unroll
        for (int i = 0; i < 4; i++) {
            int fidx = i * 256 + tid;          // 1024 float4 slots
            int row = fidx >> 3, c4 = fidx & 7;
            int grow = block_row + row;
            float4 v = make_float4(0.f, 0.f, 0.f, 0.f);
            if (grow < M)
                v = *(const float4*)(x + (size_t)grow * F_IN + c * KC + c4 * 4);
            uint32_t base = row * ASU + c4 * 2;
            *(uint2*)&smu[SM_A + base] =
                make_uint2(pack_h2(v.x, v.y), pack_h2(v.z, v.w));
        }
        // ---- B: 128 n-rows x 32 k (fp16 in gmem) ----
        {
            int fidx = tid;                    // 256 uint4 slots
            int row = fidx >> 1, q = fidx & 1;
            const size_t go = (size_t)row * (F_IN / 2) + c * (KC / 2) + q * 8;
            uint4 vh0 = *(const uint4*)(bhu + go);
            uint4 vh1 = *(const uint4*)(bhu + go + 4);
            uint32_t base = row * ASU + q * 8;
            *(uint4*)&smu[SM_BH + base] = vh0;
            *(uint4*)&smu[SM_BH + base + 4] = vh1;
        }
        __syncthreads();

        #pragma unroll
        for (int kp = 0; kp < KC / 2; kp += 8) {   // two k16 steps
            uint32_t a[2][4];
            #pragma unroll
            for (int mt = 0; mt < 2; mt++) {
                int r0 = (wm * 32 + mt * 16 + g) * ASU + kp + t;
                int r8 = (wm * 32 + mt * 16 + g + 8) * ASU + kp + t;
                a[mt][0] = smu[SM_A + r0];
                a[mt][1] = smu[SM_A + r8];
                a[mt][2] = smu[SM_A + r0 + 4];
                a[mt][3] = smu[SM_A + r8 + 4];
            }
            #pragma unroll
            for (int nt = 0; nt < 8; nt++) {
                int nrow = (wn * 64 + nt * 8 + g) * ASU + kp + t;
                uint32_t bh[2];
                bh[0] = smu[SM_BH + nrow];
                bh[1] = smu[SM_BH + nrow + 4];
                #pragma unroll
                for (int mt = 0; mt < 2; mt++)
                    mma_f16(acc[mt][nt], a[mt], bh);
            }
        }
    }

    // ---- writeback h as fp16 (one u32 = half2 per fragment pair) ----
    #pragma unroll
    for (int mt = 0; mt < 2; mt++) {
        int row0 = block_row + wm * 32 + mt * 16 + g;
        int row8 = row0 + 8;
        #pragma unroll
        for (int nt = 0; nt < 8; nt++) {
            int col = wn * 64 + nt * 8 + 2 * t;       // even
            if (row0 < M)
                hu[((size_t)row0 * F_OUT + col) >> 1] =
                    pack_h2(acc[mt][nt][0], acc[mt][nt][1]);
            if (row8 < M)
                hu[((size_t)row8 * F_OUT + col) >> 1] =
                    pack_h2(acc[mt][nt][2], acc[mt][nt][3]);
        }
    }
}

// ---------------------------------------------------------------------------
// Kernel 3: CSR aggregation — EXACT R9 version: one warp per node,
// ONE edge per j-step, all 32 lanes gather the same h row (uint2 = 4 halves
// per lane -> one coalesced 256 B request per edge); fp32 accumulation.
// ---------------------------------------------------------------------------
__global__ __launch_bounds__(256)
void aggregate_kernel(const __half* __restrict__ h16,
                      const float* __restrict__ bias,
                      float* __restrict__ out, int N) {
    const int warp = (blockIdx.x * blockDim.x + threadIdx.x) >> 5;
    const int lane = threadIdx.x & 31;
    if (warp >= N) return;

    const int s0 = g_off[warp];
    const int s1 = g_off[warp + 1];
    float4 acc = ((const float4*)bias)[lane];

    for (int base = s0; base < s1; base += 32) {
        int s = 0; float v = 0.0f;
        if (base + lane < s1) {
            int2 e = g_edge[base + lane];
            s = e.x;
            v = __int_as_float(e.y);
        }
        const int cnt = min(32, s1 - base);
        #pragma unroll 4
        for (int j = 0; j < cnt; j++) {
            int   ss = __shfl_sync(0xFFFFFFFFu, s, j);
            float vv = __shfl_sync(0xFFFFFFFFu, v, j);
            uint2 raw = ((const uint2*)(h16 + (size_t)ss * F_OUT))[lane];
            float2 f0 = __half22float2(*(const __half2*)&raw.x);
            float2 f1 = __half22float2(*(const __half2*)&raw.y);
            acc.x += f0.x * vv; acc.y += f0.y * vv;
            acc.z += f1.x * vv; acc.w += f1.y * vv;
        }
    }
    ((float4*)(out + (size_t)warp * F_OUT))[lane] = acc;
}

// ---------------------------------------------------------------------------
// Launch.  Inputs: x[f32], edge_src[i32], edge_dst[i32], edge_vals[f32],
//                  kernel[f32], bias[f32]
// CSR build forked onto a side stream, overlapped with wsplit+GEMM.
// ---------------------------------------------------------------------------
extern "C" void kernel_launch(void* const* d_in, const int* in_sizes, int n_in,
                              void* d_out, int out_size) {
    const float* x    = (const float*)d_in[0];
    const int*   esrc = (const int*)d_in[1];
    const int*   edst = (const int*)d_in[2];
    const float* eval = (const float*)d_in[3];
    const float* w    = (const float*)d_in[4];
    const float* bias = (const float*)d_in[5];
    float*       out  = (float*)d_out;

    const int M = in_sizes[0] / F_IN;     // 100000 nodes
    const int E = in_sizes[1];            // 1.6M edges
    const int n_pad  = ((M + SCAN_BLK - 1) / SCAN_BLK) * SCAN_BLK;
    const int n_sblk = n_pad / SCAN_BLK;  // 98

    __half *h16, *bh;
    cudaGetSymbolAddress((void**)&h16, g_h16);
    cudaGetSymbolAddress((void**)&bh,  g_Bh16);

    static cudaStream_t s2 = nullptr;
    static cudaEvent_t ev_fork = nullptr, ev_join = nullptr;
    static int init_done = 0;
    if (!init_done) {
        cudaStreamCreateWithFlags(&s2, cudaStreamNonBlocking);
        cudaEventCreateWithFlags(&ev_fork, cudaEventDisableTiming);
        cudaEventCreateWithFlags(&ev_join, cudaEventDisableTiming);
        cudaFuncSetAttribute(gemm_mma_kernel,
                             cudaFuncAttributeMaxDynamicSharedMemorySize,
                             GEMM_SMEM_BYTES);
        init_done = 1;
    }

    // ---- fork: CSR build on s2 ----
    cudaEventRecord(ev_fork, 0);
    cudaStreamWaitEvent(s2, ev_fork, 0);
    zero_cnt_kernel<<<(n_pad + 255) / 256, 256, 0, s2>>>(n_pad);
    count_kernel<<<(E / 4 + 255) / 256, 256, 0, s2>>>(edst, E);
    scanA_kernel<<<n_sblk, SCAN_BLK, 0, s2>>>();
    scanB_kernel<<<1, 256, 0, s2>>>(n_sblk);
    scanC_kernel<<<(M + 256) / 256, 256, 0, s2>>>(M, E);
    fill_kernel<<<(E / 4 + 255) / 256, 256, 0, s2>>>(edst, esrc, eval, E);
    cudaEventRecord(ev_join, s2);

    // ---- main stream: dense path ----
    wsplit_kernel<<<F_IN, F_OUT>>>(w, bh);
    {
        int blocks = (M + 127) / 128;
        gemm_mma_kernel<<<blocks, 256, GEMM_SMEM_BYTES>>>(x, bh, h16, M);
    }

    // ---- join, then aggregate ----
    cudaStreamWaitEvent(0, ev_join, 0);
    {
        int blocks = (M * 32 + 255) / 256;   // 12500
        aggregate_kernel<<<blocks, 256>>>(h16, bias, out, M);
    }
}